// round 13
// baseline (speedup 1.0000x reference)
#include <cuda_runtime.h>

// InverseHaar: input (B=16, C=256, H=128, W=128) fp32, C = 4 bands x G=64 groups.
// Output (B=16, G=64, 2H=256, 2W=256) fp32.
//
// SMEM-staged variant: each 256-thread block handles an 8-row tile of one
// (b,g). Load phase: threads are split into 4 groups of 64; group k streams
// band k's 8x128 tile (4KB) as 4 fully-contiguous 1KB bursts into SMEM ->
// each warp reads ONE DRAM stream (vs 4 in the direct kernel), testing
// whether read-stream count / row-buffer locality is the source of the ~18%
// DRAM-efficiency loss. Compute phase: conflict-free SMEM float2 reads,
// warp-contiguous 512B STG.128 stores (unchanged from converged kernel).

#define B_  16
#define G_  64
#define H_  128
#define W_  128
#define HW_ (H_ * W_)              // 16384
#define OW_ (2 * W_)               // 256 output width
#define OH_ (2 * H_)               // 256 output height

#define TILE_H_   8                // input rows per block
#define TILE_F4_  (TILE_H_ * W_ / 4)   // 256 float4 per band tile
#define TILE_F2_  (TILE_H_ * W_ / 2)   // 512 float2 per band tile

__global__ void __launch_bounds__(256) inverse_haar_kernel(
    const float4* __restrict__ in,   // viewed as float4
    float4* __restrict__ out)        // viewed as float4
{
    __shared__ float4 s_band[4][TILE_F4_];   // 4 x 4KB = 16KB

    unsigned tid = threadIdx.x;

    // Block -> (b, g, tile)
    unsigned bid  = blockIdx.x;
    unsigned tile = bid & 15;            // H / TILE_H_ = 16
    unsigned g    = (bid >> 4) & (G_ - 1);
    unsigned b    = bid >> 10;
    unsigned h0   = tile * TILE_H_;

    // ---- Load phase: group k (64 threads) loads band k contiguously ----
    {
        unsigned band = tid >> 6;        // 0..3
        unsigned i    = tid & 63;        // 0..63
        // Band tile base in float4 units: ((b*4+band)*G + g)*(HW/4) + h0*(W/4)
        unsigned base = ((b * 4 + band) * G_ + g) * (HW_ / 4) + h0 * (W_ / 4);
        #pragma unroll
        for (int j = 0; j < 4; j++) {
            // each step: 64 consecutive float4 = 1KB contiguous burst
            s_band[band][j * 64 + i] = __ldcs(&in[base + j * 64 + i]);
        }
    }
    __syncthreads();

    // ---- Compute phase: thread = (r, l); lane l handles w pairs {2l,2l+1}
    //      and {64+2l, 64+2l+1} of tile row r ----
    unsigned l = tid & 31;
    unsigned r = tid >> 5;               // 0..7

    const float2* sa = (const float2*)s_band[0];
    const float2* sh = (const float2*)s_band[1];
    const float2* sv = (const float2*)s_band[2];
    const float2* sd = (const float2*)s_band[3];

    unsigned i0 = r * (W_ / 2) + l;      // half 0
    unsigned i1 = i0 + 32;               // half 1

    float2 a0 = sa[i0], a1 = sa[i1];
    float2 h0v = sh[i0], h1v = sh[i1];
    float2 v0 = sv[i0], v1 = sv[i1];
    float2 d0 = sd[i0], d1 = sd[i1];

    const float Q = 0.25f;

    float tl0x = (a0.x + h0v.x + v0.x + d0.x) * Q;
    float tr0x = (a0.x - h0v.x + v0.x - d0.x) * Q;
    float bl0x = (a0.x + h0v.x - v0.x - d0.x) * Q;
    float br0x = (a0.x - h0v.x - v0.x + d0.x) * Q;

    float tl0y = (a0.y + h0v.y + v0.y + d0.y) * Q;
    float tr0y = (a0.y - h0v.y + v0.y - d0.y) * Q;
    float bl0y = (a0.y + h0v.y - v0.y - d0.y) * Q;
    float br0y = (a0.y - h0v.y - v0.y + d0.y) * Q;

    float tl1x = (a1.x + h1v.x + v1.x + d1.x) * Q;
    float tr1x = (a1.x - h1v.x + v1.x - d1.x) * Q;
    float bl1x = (a1.x + h1v.x - v1.x - d1.x) * Q;
    float br1x = (a1.x - h1v.x - v1.x + d1.x) * Q;

    float tl1y = (a1.y + h1v.y + v1.y + d1.y) * Q;
    float tr1y = (a1.y - h1v.y + v1.y - d1.y) * Q;
    float bl1y = (a1.y + h1v.y - v1.y - d1.y) * Q;
    float br1y = (a1.y - h1v.y - v1.y + d1.y) * Q;

    // Output rows 2*(h0+r), 2*(h0+r)+1; row = OW_/4 = 64 float4.
    unsigned orow0 = ((b * G_ + g) * OH_ + 2 * (h0 + r)) * (OW_ / 4);
    unsigned orow1 = orow0 + (OW_ / 4);

    // Warp-contiguous 512B stores (slots l and 32+l per row).
    __stcs(&out[orow0 + l],      make_float4(tl0x, tr0x, tl0y, tr0y));
    __stcs(&out[orow0 + 32 + l], make_float4(tl1x, tr1x, tl1y, tr1y));
    __stcs(&out[orow1 + l],      make_float4(bl0x, br0x, bl0y, br0y));
    __stcs(&out[orow1 + 32 + l], make_float4(bl1x, br1x, bl1y, br1y));
}

extern "C" void kernel_launch(void* const* d_in, const int* in_sizes, int n_in,
                              void* d_out, int out_size)
{
    const float4* in = (const float4*)d_in[0];
    float4* out = (float4*)d_out;

    int grid = B_ * G_ * (H_ / TILE_H_);   // 16 * 64 * 16 = 16384
    inverse_haar_kernel<<<grid, 256>>>(in, out);
}

// round 14
// speedup vs baseline: 1.0118x; 1.0118x over previous
#include <cuda_runtime.h>

// InverseHaar: input (B=16, C=256, H=128, W=128) fp32, C = 4 bands x G=64 groups.
// Output (B=16, G=64, 2H=256, 2W=256) fp32.
//
// FINAL (converged, best measured across 13 rounds). One thread per
// (b, g, h, half, l). Lane l handles input w in {2l, 2l+1} of the `half`-th
// half-row:
//   - 4 front-batched LDG.64 streaming loads (256B/warp/band, 4 streams)
//   - 2 STG.128 streaming stores, each warp-contiguous 512B (full-line
//     coverage -> zero RFO traffic)
// Moves the irreducible 537MB; pinned at the HBM3e mixed 1:1 read/write
// streaming wall (~6.45-6.50 TB/s, ~81.5% DRAM-active). Ceiling proven
// invariant to: access pattern (direct 4-stream vs SMEM-staged 1-stream),
// MLP (4/8/16), occupancy (51-92%), block size (256/512), persistent vs
// classic scheduling, L1/L2 cache policies, and addressing width.
// 32-bit addressing (max offset 2^27 elements < 2^31).

#define B_  16
#define G_  64
#define H_  128
#define W_  128
#define HW_ (H_ * W_)              // 16384
#define BAND_STRIDE_ (G_ * HW_)    // 1048576 floats between bands (same b)
#define OW_ (2 * W_)               // 256 output width
#define OH_ (2 * H_)               // 256 output height

__global__ void __launch_bounds__(256) inverse_haar_kernel(
    const float2* __restrict__ in,   // viewed as float2
    float4* __restrict__ out)        // viewed as float4
{
    unsigned idx = blockIdx.x * blockDim.x + threadIdx.x;
    // total threads = B*G*H*2*32 = 8,388,608

    unsigned l    = idx & 31;       // lane: w pair within half-row
    unsigned t    = idx >> 5;
    unsigned half = t & 1;          // which half of the input row (w<64 or w>=64)
    t >>= 1;
    unsigned h    = t & (H_ - 1);
    t >>= 7;
    unsigned g    = t & (G_ - 1);
    unsigned b    = t >> 6;

    // Input base in float2 units: band a, (b,g,h) row, pair index half*32 + l.
    unsigned base = (b * 4 * G_ + g) * (HW_ / 2) + h * (W_ / 2) + half * 32 + l;
    const unsigned S = BAND_STRIDE_ / 2;   // band stride in float2 units

    // 4 independent streaming loads (MLP_p1 = 4)
    float2 va = __ldcs(&in[base]);
    float2 vh = __ldcs(&in[base + S]);
    float2 vv = __ldcs(&in[base + 2 * S]);
    float2 vd = __ldcs(&in[base + 3 * S]);

    const float Q = 0.25f;

    float tlx = (va.x + vh.x + vv.x + vd.x) * Q;
    float trx = (va.x - vh.x + vv.x - vd.x) * Q;
    float blx = (va.x + vh.x - vv.x - vd.x) * Q;
    float brx = (va.x - vh.x - vv.x + vd.x) * Q;

    float tly = (va.y + vh.y + vv.y + vd.y) * Q;
    float try_ = (va.y - vh.y + vv.y - vd.y) * Q;
    float bly = (va.y + vh.y - vv.y - vd.y) * Q;
    float bry = (va.y - vh.y - vv.y + vd.y) * Q;

    // Output row bases (float4 units). Row has OW_/4 = 64 float4.
    // This thread's float4 slot within the row: half*32 + l.
    unsigned orow0 = ((b * G_ + g) * OH_ + 2 * h) * (OW_ / 4) + half * 32 + l;
    unsigned orow1 = orow0 + (OW_ / 4);

    // Each store: lanes 0..31 hit consecutive 16B slots -> contiguous 512B.
    __stcs(&out[orow0], make_float4(tlx, trx, tly, try_));
    __stcs(&out[orow1], make_float4(blx, brx, bly, bry));
}

extern "C" void kernel_launch(void* const* d_in, const int* in_sizes, int n_in,
                              void* d_out, int out_size)
{
    const float2* in = (const float2*)d_in[0];
    float4* out = (float4*)d_out;

    int total_threads = B_ * G_ * H_ * 2 * 32;   // 8,388,608
    int block = 256;
    int grid = total_threads / block;            // 32768
    inverse_haar_kernel<<<grid, block>>>(in, out);
}